// round 7
// baseline (speedup 1.0000x reference)
#include <cuda_runtime.h>
#include <cuda_bf16.h>
#include <cstdint>

#define N_NODES 40000
#define N_EDGES 640000
#define DIN 128
#define DOUT 64

__device__ float g_t0[N_NODES * DOUT];
__device__ float g_t1[N_NODES * DOUT];
__device__ float g_Wc[DIN * DOUT];
__device__ int   g_row_ptr[N_NODES + 1];

// row_ptr[n] = lower_bound(dst, n); dst is sorted.
__global__ void build_row_ptr_kernel(const int* __restrict__ dst) {
    int n = blockIdx.x * blockDim.x + threadIdx.x;
    if (n > N_NODES) return;
    int lo = 0, hi = N_EDGES;
    while (lo < hi) {
        int mid = (lo + hi) >> 1;
        if (dst[mid] < n) lo = mid + 1;
        else hi = mid;
    }
    g_row_ptr[n] = lo;
}

// Wc = (W1 @ W2) @ W3 in one kernel. 128 blocks (one output row), 128 threads.
__global__ void __launch_bounds__(128)
wc_kernel(const float* __restrict__ W1, const float* __restrict__ W2,
          const float* __restrict__ W3) {
    __shared__ float sW2[DIN * DIN];
    __shared__ float row[DIN];
    __shared__ float t1[DIN];

    const int i = blockIdx.x, j = threadIdx.x;

    const float4* W24 = (const float4*)W2;
    float4* sW24 = (float4*)sW2;
    #pragma unroll
    for (int it = 0; it < 32; ++it)
        sW24[j + it * 128] = W24[j + it * 128];
    row[j] = W1[i * DIN + j];
    __syncthreads();

    float acc = 0.f;
    #pragma unroll 8
    for (int k = 0; k < DIN; ++k) acc += row[k] * sW2[k * DIN + j];
    t1[j] = acc;
    __syncthreads();

    if (j < DOUT) {
        float acc2 = 0.f;
        #pragma unroll 8
        for (int k = 0; k < DIN; ++k) acc2 += t1[k] * __ldg(&W3[k * DOUT + j]);
        g_Wc[i * DOUT + j] = acc2;
    }
}

// out[N,64] = F[N,128] @ Wc[128,64].
// 256 threads, 64x64 tile, 4x4 micro-tile, k chunked by 4 (all-LDS.128).
__global__ void __launch_bounds__(256)
gemm_fwc_kernel(const float* __restrict__ F, float* __restrict__ out) {
    __shared__ float sF[64 * DIN];
    __shared__ float sW[DIN * DOUT];

    const int tid = threadIdx.x;
    const int n0 = blockIdx.x * 64;

    const float4* F4 = (const float4*)(F + (size_t)n0 * DIN);
    float4* sF4 = (float4*)sF;
    #pragma unroll
    for (int i = 0; i < 8; ++i)
        sF4[tid + i * 256] = F4[tid + i * 256];
    const float4* W4 = (const float4*)g_Wc;
    float4* sW4 = (float4*)sW;
    #pragma unroll
    for (int i = 0; i < 8; ++i)
        sW4[tid + i * 256] = W4[tid + i * 256];
    __syncthreads();

    const int tx = tid & 15;
    const int ty = tid >> 4;
    const int cj = tx * 4;
    const int ni = ty * 4;

    float acc[4][4] = {};
    #pragma unroll
    for (int k = 0; k < DIN; k += 4) {
        float4 w[4];
        #pragma unroll
        for (int j = 0; j < 4; ++j)
            w[j] = *(const float4*)&sW[(k + j) * DOUT + cj];
        float4 f[4];
        #pragma unroll
        for (int i = 0; i < 4; ++i)
            f[i] = *(const float4*)&sF[(ni + i) * DIN + k];
        #pragma unroll
        for (int i = 0; i < 4; ++i) {
            acc[i][0] += f[i].x * w[0].x + f[i].y * w[1].x + f[i].z * w[2].x + f[i].w * w[3].x;
            acc[i][1] += f[i].x * w[0].y + f[i].y * w[1].y + f[i].z * w[2].y + f[i].w * w[3].y;
            acc[i][2] += f[i].x * w[0].z + f[i].y * w[1].z + f[i].z * w[2].z + f[i].w * w[3].z;
            acc[i][3] += f[i].x * w[0].w + f[i].y * w[1].w + f[i].z * w[2].w + f[i].w * w[3].w;
        }
    }
    #pragma unroll
    for (int i = 0; i < 4; ++i) {
        float4 o = make_float4(acc[i][0], acc[i][1], acc[i][2], acc[i][3]);
        *(float4*)&out[(size_t)(n0 + ni + i) * DOUT + cj] = o;
    }
}

// Aggregation hop, width 64. Block = 256 thr = 8 warps = 8 nodes.
// Indices pre-scaled (*16 = float4 row offset) staged in smem.
// Main loop: 8 independent LDG.128 per half-thread in flight.
// Tail: 3 predicated independent loads (no serial dependent chain).
#define GCHUNK 256
__global__ void __launch_bounds__(256)
gather64_kernel(const int* __restrict__ src,
                const float* __restrict__ h_in,
                float* __restrict__ h_out) {
    __shared__ int s_idx[GCHUNK];

    const int tid  = threadIdx.x;
    const int wid  = tid >> 5;
    const int lane = tid & 31;
    const int quad = lane & 15;
    const int half = lane >> 4;

    const int n0 = blockIdx.x * 8;
    const int n  = n0 + wid;

    const int blk_beg = g_row_ptr[n0];
    const int blk_end = g_row_ptr[n0 + 8];
    const int beg = g_row_ptr[n];
    const int end = g_row_ptr[n + 1];

    const float4* in4 = (const float4*)h_in;

    float4 acc = make_float4(0.f, 0.f, 0.f, 0.f);

    for (int base = blk_beg; base < blk_end; base += GCHUNK) {
        if (base + tid < blk_end)
            s_idx[tid] = __ldg(&src[base + tid]) * 16;   // pre-scaled row offset
        __syncthreads();

        const int hi = min(end, base + GCHUNK);
        int e = max(beg, base) + half;

        // 8 edges per half-thread per iteration (16 warp-wide), all independent.
        for (; e + 14 < hi; e += 16) {
            float4 a[8];
            #pragma unroll
            for (int u = 0; u < 8; ++u)
                a[u] = __ldg(&in4[(size_t)s_idx[e + 2 * u - base] + quad]);
            acc.x += ((a[0].x + a[1].x) + (a[2].x + a[3].x)) + ((a[4].x + a[5].x) + (a[6].x + a[7].x));
            acc.y += ((a[0].y + a[1].y) + (a[2].y + a[3].y)) + ((a[4].y + a[5].y) + (a[6].y + a[7].y));
            acc.z += ((a[0].z + a[1].z) + (a[2].z + a[3].z)) + ((a[4].z + a[5].z) + (a[6].z + a[7].z));
            acc.w += ((a[0].w + a[1].w) + (a[2].w + a[3].w)) + ((a[4].w + a[5].w) + (a[6].w + a[7].w));
        }
        // 4-batch if >= 4 slots remain.
        if (e + 6 < hi) {
            float4 a[4];
            #pragma unroll
            for (int u = 0; u < 4; ++u)
                a[u] = __ldg(&in4[(size_t)s_idx[e + 2 * u - base] + quad]);
            acc.x += (a[0].x + a[1].x) + (a[2].x + a[3].x);
            acc.y += (a[0].y + a[1].y) + (a[2].y + a[3].y);
            acc.z += (a[0].z + a[1].z) + (a[2].z + a[3].z);
            acc.w += (a[0].w + a[1].w) + (a[2].w + a[3].w);
            e += 8;
        }
        // Predicated tail: <= 3 slots, independent guarded loads.
        {
            float4 t0v = make_float4(0.f,0.f,0.f,0.f);
            float4 t1v = make_float4(0.f,0.f,0.f,0.f);
            float4 t2v = make_float4(0.f,0.f,0.f,0.f);
            if (e < hi)     t0v = __ldg(&in4[(size_t)s_idx[e     - base] + quad]);
            if (e + 2 < hi) t1v = __ldg(&in4[(size_t)s_idx[e + 2 - base] + quad]);
            if (e + 4 < hi) t2v = __ldg(&in4[(size_t)s_idx[e + 4 - base] + quad]);
            acc.x += (t0v.x + t1v.x) + t2v.x;
            acc.y += (t0v.y + t1v.y) + t2v.y;
            acc.z += (t0v.z + t1v.z) + t2v.z;
            acc.w += (t0v.w + t1v.w) + t2v.w;
        }
        __syncthreads();
    }

    acc.x += __shfl_down_sync(0xffffffffu, acc.x, 16);
    acc.y += __shfl_down_sync(0xffffffffu, acc.y, 16);
    acc.z += __shfl_down_sync(0xffffffffu, acc.z, 16);
    acc.w += __shfl_down_sync(0xffffffffu, acc.w, 16);

    if (half == 0)
        ((float4*)h_out)[(size_t)n * 16 + quad] = acc;
}

extern "C" void kernel_launch(void* const* d_in, const int* in_sizes, int n_in,
                              void* d_out, int out_size) {
    const int*   src      = (const int*)d_in[0];
    const int*   dst      = (const int*)d_in[1];
    const float* features = (const float*)d_in[2];
    const float* W1       = (const float*)d_in[3];
    const float* W2       = (const float*)d_in[4];
    const float* W3       = (const float*)d_in[5];
    float*       out      = (float*)d_out;

    float* t0; float* t1;
    cudaGetSymbolAddress((void**)&t0, g_t0);
    cudaGetSymbolAddress((void**)&t1, g_t1);

    build_row_ptr_kernel<<<(N_NODES + 1 + 255) / 256, 256>>>(dst);
    wc_kernel<<<DIN, DIN>>>(W1, W2, W3);

    gemm_fwc_kernel<<<N_NODES / 64, 256>>>(features, t0);

    const int gblocks = N_NODES / 8;   // 5000
    gather64_kernel<<<gblocks, 256>>>(src, t0, t1);
    gather64_kernel<<<gblocks, 256>>>(src, t1, t0);
    gather64_kernel<<<gblocks, 256>>>(src, t0, out);
}

// round 8
// speedup vs baseline: 1.0851x; 1.0851x over previous
#include <cuda_runtime.h>
#include <cuda_fp16.h>
#include <cuda_bf16.h>
#include <cstdint>

#define N_NODES 40000
#define N_EDGES 640000
#define DIN 128
#define DOUT 64

// fp16 intermediates (row = 64 halves = 128 B = 16 uint2)
__device__ __half g_t0[N_NODES * DOUT];
__device__ __half g_t1[N_NODES * DOUT];
__device__ float  g_Wc[DIN * DOUT];
__device__ int    g_row_ptr[N_NODES + 1];

// row_ptr[n] = lower_bound(dst, n); dst is sorted.
__global__ void build_row_ptr_kernel(const int* __restrict__ dst) {
    int n = blockIdx.x * blockDim.x + threadIdx.x;
    if (n > N_NODES) return;
    int lo = 0, hi = N_EDGES;
    while (lo < hi) {
        int mid = (lo + hi) >> 1;
        if (dst[mid] < n) lo = mid + 1;
        else hi = mid;
    }
    g_row_ptr[n] = lo;
}

// Wc = (W1 @ W2) @ W3 in one kernel.
__global__ void __launch_bounds__(128)
wc_kernel(const float* __restrict__ W1, const float* __restrict__ W2,
          const float* __restrict__ W3) {
    __shared__ float sW2[DIN * DIN];
    __shared__ float row[DIN];
    __shared__ float t1[DIN];

    const int i = blockIdx.x, j = threadIdx.x;

    const float4* W24 = (const float4*)W2;
    float4* sW24 = (float4*)sW2;
    #pragma unroll
    for (int it = 0; it < 32; ++it)
        sW24[j + it * 128] = W24[j + it * 128];
    row[j] = W1[i * DIN + j];
    __syncthreads();

    float acc = 0.f;
    #pragma unroll 8
    for (int k = 0; k < DIN; ++k) acc += row[k] * sW2[k * DIN + j];
    t1[j] = acc;
    __syncthreads();

    if (j < DOUT) {
        float acc2 = 0.f;
        #pragma unroll 8
        for (int k = 0; k < DIN; ++k) acc2 += t1[k] * __ldg(&W3[k * DOUT + j]);
        g_Wc[i * DOUT + j] = acc2;
    }
}

// t0[N,64](fp16) = F[N,128](fp32) @ Wc[128,64](fp32).
// 256 threads, 64x64 tile, 4x4 micro-tile, k chunked by 4 (all-LDS.128).
__global__ void __launch_bounds__(256)
gemm_fwc_kernel(const float* __restrict__ F, __half* __restrict__ out) {
    __shared__ float sF[64 * DIN];
    __shared__ float sW[DIN * DOUT];

    const int tid = threadIdx.x;
    const int n0 = blockIdx.x * 64;

    const float4* F4 = (const float4*)(F + (size_t)n0 * DIN);
    float4* sF4 = (float4*)sF;
    #pragma unroll
    for (int i = 0; i < 8; ++i)
        sF4[tid + i * 256] = F4[tid + i * 256];
    const float4* W4 = (const float4*)g_Wc;
    float4* sW4 = (float4*)sW;
    #pragma unroll
    for (int i = 0; i < 8; ++i)
        sW4[tid + i * 256] = W4[tid + i * 256];
    __syncthreads();

    const int tx = tid & 15;
    const int ty = tid >> 4;
    const int cj = tx * 4;
    const int ni = ty * 4;

    float acc[4][4] = {};
    #pragma unroll
    for (int k = 0; k < DIN; k += 4) {
        float4 w[4];
        #pragma unroll
        for (int j = 0; j < 4; ++j)
            w[j] = *(const float4*)&sW[(k + j) * DOUT + cj];
        float4 f[4];
        #pragma unroll
        for (int i = 0; i < 4; ++i)
            f[i] = *(const float4*)&sF[(ni + i) * DIN + k];
        #pragma unroll
        for (int i = 0; i < 4; ++i) {
            acc[i][0] += f[i].x * w[0].x + f[i].y * w[1].x + f[i].z * w[2].x + f[i].w * w[3].x;
            acc[i][1] += f[i].x * w[0].y + f[i].y * w[1].y + f[i].z * w[2].y + f[i].w * w[3].y;
            acc[i][2] += f[i].x * w[0].z + f[i].y * w[1].z + f[i].z * w[2].z + f[i].w * w[3].z;
            acc[i][3] += f[i].x * w[0].w + f[i].y * w[1].w + f[i].z * w[2].w + f[i].w * w[3].w;
        }
    }
    #pragma unroll
    for (int i = 0; i < 4; ++i) {
        __half2 o0 = __floats2half2_rn(acc[i][0], acc[i][1]);
        __half2 o1 = __floats2half2_rn(acc[i][2], acc[i][3]);
        uint2 o;
        o.x = *reinterpret_cast<unsigned*>(&o0);
        o.y = *reinterpret_cast<unsigned*>(&o1);
        *(uint2*)&out[(size_t)(n0 + ni + i) * DOUT + cj] = o;
    }
}

__device__ __forceinline__ void acc_h4(float4& acc, uint2 r) {
    __half2 h0 = *reinterpret_cast<__half2*>(&r.x);
    __half2 h1 = *reinterpret_cast<__half2*>(&r.y);
    float2 f0 = __half22float2(h0);
    float2 f1 = __half22float2(h1);
    acc.x += f0.x; acc.y += f0.y; acc.z += f1.x; acc.w += f1.y;
}

// Aggregation hop, fp16 input rows (128 B), fp32 accumulation.
// Block = 256 thr = 8 warps = 8 nodes; indices pre-scaled (*16 = uint2 row base).
// OUT_HALF=1 -> write fp16 row; OUT_HALF=0 -> write fp32 row (final layer).
#define GCHUNK 256
template <int OUT_HALF>
__global__ void __launch_bounds__(256)
gather_h_kernel(const int* __restrict__ src,
                const __half* __restrict__ h_in,
                void* __restrict__ h_out) {
    __shared__ int s_idx[GCHUNK];

    const int tid  = threadIdx.x;
    const int wid  = tid >> 5;
    const int lane = tid & 31;
    const int quad = lane & 15;
    const int half = lane >> 4;

    const int n0 = blockIdx.x * 8;
    const int n  = n0 + wid;

    const int blk_beg = g_row_ptr[n0];
    const int blk_end = g_row_ptr[n0 + 8];
    const int beg = g_row_ptr[n];
    const int end = g_row_ptr[n + 1];

    const uint2* in2 = (const uint2*)h_in;

    float4 acc = make_float4(0.f, 0.f, 0.f, 0.f);

    for (int base = blk_beg; base < blk_end; base += GCHUNK) {
        if (base + tid < blk_end)
            s_idx[tid] = __ldg(&src[base + tid]) * 16;   // uint2 row base
        __syncthreads();

        const int hi = min(end, base + GCHUNK);
        int e = max(beg, base) + half;

        // 8 edges per half-thread in flight.
        for (; e + 14 < hi; e += 16) {
            uint2 a[8];
            #pragma unroll
            for (int u = 0; u < 8; ++u)
                a[u] = __ldg(&in2[(size_t)s_idx[e + 2 * u - base] + quad]);
            #pragma unroll
            for (int u = 0; u < 8; ++u)
                acc_h4(acc, a[u]);
        }
        if (e + 6 < hi) {
            uint2 a[4];
            #pragma unroll
            for (int u = 0; u < 4; ++u)
                a[u] = __ldg(&in2[(size_t)s_idx[e + 2 * u - base] + quad]);
            #pragma unroll
            for (int u = 0; u < 4; ++u)
                acc_h4(acc, a[u]);
            e += 8;
        }
        { // predicated tail, <= 3 slots, independent loads (zero half2 == 0.0f)
            uint2 t0v = make_uint2(0u, 0u), t1v = make_uint2(0u, 0u), t2v = make_uint2(0u, 0u);
            if (e < hi)     t0v = __ldg(&in2[(size_t)s_idx[e     - base] + quad]);
            if (e + 2 < hi) t1v = __ldg(&in2[(size_t)s_idx[e + 2 - base] + quad]);
            if (e + 4 < hi) t2v = __ldg(&in2[(size_t)s_idx[e + 4 - base] + quad]);
            acc_h4(acc, t0v); acc_h4(acc, t1v); acc_h4(acc, t2v);
        }
        __syncthreads();
    }

    acc.x += __shfl_down_sync(0xffffffffu, acc.x, 16);
    acc.y += __shfl_down_sync(0xffffffffu, acc.y, 16);
    acc.z += __shfl_down_sync(0xffffffffu, acc.z, 16);
    acc.w += __shfl_down_sync(0xffffffffu, acc.w, 16);

    if (half == 0) {
        if (OUT_HALF) {
            __half2 o0 = __floats2half2_rn(acc.x, acc.y);
            __half2 o1 = __floats2half2_rn(acc.z, acc.w);
            uint2 o;
            o.x = *reinterpret_cast<unsigned*>(&o0);
            o.y = *reinterpret_cast<unsigned*>(&o1);
            ((uint2*)h_out)[(size_t)n * 16 + quad] = o;
        } else {
            ((float4*)h_out)[(size_t)n * 16 + quad] = acc;
        }
    }
}

extern "C" void kernel_launch(void* const* d_in, const int* in_sizes, int n_in,
                              void* d_out, int out_size) {
    const int*   src      = (const int*)d_in[0];
    const int*   dst      = (const int*)d_in[1];
    const float* features = (const float*)d_in[2];
    const float* W1       = (const float*)d_in[3];
    const float* W2       = (const float*)d_in[4];
    const float* W3       = (const float*)d_in[5];

    __half* t0; __half* t1;
    cudaGetSymbolAddress((void**)&t0, g_t0);
    cudaGetSymbolAddress((void**)&t1, g_t1);

    build_row_ptr_kernel<<<(N_NODES + 1 + 255) / 256, 256>>>(dst);
    wc_kernel<<<DIN, DIN>>>(W1, W2, W3);

    gemm_fwc_kernel<<<N_NODES / 64, 256>>>(features, t0);

    const int gblocks = N_NODES / 8;   // 5000
    gather_h_kernel<1><<<gblocks, 256>>>(src, t0, t1);
    gather_h_kernel<1><<<gblocks, 256>>>(src, t1, t0);
    gather_h_kernel<0><<<gblocks, 256>>>(src, t0, d_out);
}

// round 9
// speedup vs baseline: 1.1168x; 1.0292x over previous
#include <cuda_runtime.h>
#include <cuda_fp16.h>
#include <cuda_bf16.h>
#include <cstdint>

#define N_NODES 40000
#define N_EDGES 640000
#define DIN 128
#define DOUT 64

// fp16 intermediates (row = 64 halves = 128 B = 8 uint4)
__device__ __half g_t0[N_NODES * DOUT];
__device__ __half g_t1[N_NODES * DOUT];
__device__ float  g_Wc[DIN * DOUT];
__device__ int    g_row_ptr[N_NODES + 1];

// row_ptr[n] = lower_bound(dst, n); dst is sorted.
__global__ void build_row_ptr_kernel(const int* __restrict__ dst) {
    int n = blockIdx.x * blockDim.x + threadIdx.x;
    if (n > N_NODES) return;
    int lo = 0, hi = N_EDGES;
    while (lo < hi) {
        int mid = (lo + hi) >> 1;
        if (dst[mid] < n) lo = mid + 1;
        else hi = mid;
    }
    g_row_ptr[n] = lo;
}

// Wc = (W1 @ W2) @ W3 in one kernel.
__global__ void __launch_bounds__(128)
wc_kernel(const float* __restrict__ W1, const float* __restrict__ W2,
          const float* __restrict__ W3) {
    __shared__ float sW2[DIN * DIN];
    __shared__ float row[DIN];
    __shared__ float t1[DIN];

    const int i = blockIdx.x, j = threadIdx.x;

    const float4* W24 = (const float4*)W2;
    float4* sW24 = (float4*)sW2;
    #pragma unroll
    for (int it = 0; it < 32; ++it)
        sW24[j + it * 128] = W24[j + it * 128];
    row[j] = W1[i * DIN + j];
    __syncthreads();

    float acc = 0.f;
    #pragma unroll 8
    for (int k = 0; k < DIN; ++k) acc += row[k] * sW2[k * DIN + j];
    t1[j] = acc;
    __syncthreads();

    if (j < DOUT) {
        float acc2 = 0.f;
        #pragma unroll 8
        for (int k = 0; k < DIN; ++k) acc2 += t1[k] * __ldg(&W3[k * DOUT + j]);
        g_Wc[i * DOUT + j] = acc2;
    }
}

// t0[N,64](fp16) = F[N,128](fp32) @ Wc[128,64](fp32).
__global__ void __launch_bounds__(256)
gemm_fwc_kernel(const float* __restrict__ F, __half* __restrict__ out) {
    __shared__ float sF[64 * DIN];
    __shared__ float sW[DIN * DOUT];

    const int tid = threadIdx.x;
    const int n0 = blockIdx.x * 64;

    const float4* F4 = (const float4*)(F + (size_t)n0 * DIN);
    float4* sF4 = (float4*)sF;
    #pragma unroll
    for (int i = 0; i < 8; ++i)
        sF4[tid + i * 256] = F4[tid + i * 256];
    const float4* W4 = (const float4*)g_Wc;
    float4* sW4 = (float4*)sW;
    #pragma unroll
    for (int i = 0; i < 8; ++i)
        sW4[tid + i * 256] = W4[tid + i * 256];
    __syncthreads();

    const int tx = tid & 15;
    const int ty = tid >> 4;
    const int cj = tx * 4;
    const int ni = ty * 4;

    float acc[4][4] = {};
    #pragma unroll
    for (int k = 0; k < DIN; k += 4) {
        float4 w[4];
        #pragma unroll
        for (int j = 0; j < 4; ++j)
            w[j] = *(const float4*)&sW[(k + j) * DOUT + cj];
        float4 f[4];
        #pragma unroll
        for (int i = 0; i < 4; ++i)
            f[i] = *(const float4*)&sF[(ni + i) * DIN + k];
        #pragma unroll
        for (int i = 0; i < 4; ++i) {
            acc[i][0] += f[i].x * w[0].x + f[i].y * w[1].x + f[i].z * w[2].x + f[i].w * w[3].x;
            acc[i][1] += f[i].x * w[0].y + f[i].y * w[1].y + f[i].z * w[2].y + f[i].w * w[3].y;
            acc[i][2] += f[i].x * w[0].z + f[i].y * w[1].z + f[i].z * w[2].z + f[i].w * w[3].z;
            acc[i][3] += f[i].x * w[0].w + f[i].y * w[1].w + f[i].z * w[2].w + f[i].w * w[3].w;
        }
    }
    #pragma unroll
    for (int i = 0; i < 4; ++i) {
        __half2 o0 = __floats2half2_rn(acc[i][0], acc[i][1]);
        __half2 o1 = __floats2half2_rn(acc[i][2], acc[i][3]);
        uint2 o;
        o.x = *reinterpret_cast<unsigned*>(&o0);
        o.y = *reinterpret_cast<unsigned*>(&o1);
        *(uint2*)&out[(size_t)(n0 + ni + i) * DOUT + cj] = o;
    }
}

// --- fp16 helpers ---
__device__ __forceinline__ __half2 u2h(unsigned v) { return *reinterpret_cast<__half2*>(&v); }
__device__ __forceinline__ unsigned h2u(__half2 v) { return *reinterpret_cast<unsigned*>(&v); }

// pairwise fp16 add of two rows' octants (4x HADD2)
__device__ __forceinline__ uint4 hmerge(uint4 x, uint4 y) {
    uint4 r;
    r.x = h2u(__hadd2(u2h(x.x), u2h(y.x)));
    r.y = h2u(__hadd2(u2h(x.y), u2h(y.y)));
    r.z = h2u(__hadd2(u2h(x.z), u2h(y.z)));
    r.w = h2u(__hadd2(u2h(x.w), u2h(y.w)));
    return r;
}

// accumulate 8 halves (uint4) into 8 fp32 accumulators
__device__ __forceinline__ void hacc(float* a, uint4 v) {
    float2 f;
    f = __half22float2(u2h(v.x)); a[0] += f.x; a[1] += f.y;
    f = __half22float2(u2h(v.y)); a[2] += f.x; a[3] += f.y;
    f = __half22float2(u2h(v.z)); a[4] += f.x; a[5] += f.y;
    f = __half22float2(u2h(v.w)); a[6] += f.x; a[7] += f.y;
}

// Aggregation hop, fp16 rows (128 B = 8 uint4), fp32 accumulation.
// Block = 256 thr = 8 warps = 8 nodes. Warp lane = (slot 0..3, oct 0..7):
// 4 edge slots x uint4 octant. Main batch = 16 edges (4 loads/lane).
// First reduction level in fp16 (HADD2) halves the convert/add stream.
#define GCHUNK 256
template <int OUT_HALF>
__global__ void __launch_bounds__(256)
gather_h_kernel(const int* __restrict__ src,
                const __half* __restrict__ h_in,
                void* __restrict__ h_out) {
    __shared__ int s_idx[GCHUNK];

    const int tid  = threadIdx.x;
    const int wid  = tid >> 5;
    const int lane = tid & 31;
    const int oct  = lane & 7;    // uint4 within row
    const int slot = lane >> 3;   // edge slot 0..3

    const int n0 = blockIdx.x * 8;
    const int n  = n0 + wid;

    const int blk_beg = g_row_ptr[n0];
    const int blk_end = g_row_ptr[n0 + 8];
    const int beg = g_row_ptr[n];
    const int end = g_row_ptr[n + 1];

    const uint4* in4 = (const uint4*)h_in;   // row = 8 uint4

    float a[8] = {};

    for (int base = blk_beg; base < blk_end; base += GCHUNK) {
        if (base + tid < blk_end)
            s_idx[tid] = __ldg(&src[base + tid]) * 8;   // uint4 row base
        __syncthreads();

        const int hi = min(end, base + GCHUNK);
        int off = max(beg, base) - base;                // smem offset
        int r = hi - (base + off);                      // edges this chunk

        // main: 16 edges per warp-iter, 4 independent LDG.128 per lane
        while (r >= 16) {
            uint4 v0 = __ldg(&in4[(size_t)s_idx[off + slot     ] + oct]);
            uint4 v1 = __ldg(&in4[(size_t)s_idx[off + slot +  4] + oct]);
            uint4 v2 = __ldg(&in4[(size_t)s_idx[off + slot +  8] + oct]);
            uint4 v3 = __ldg(&in4[(size_t)s_idx[off + slot + 12] + oct]);
            hacc(a, hmerge(v0, v1));
            hacc(a, hmerge(v2, v3));
            off += 16; r -= 16;
        }
        if (r >= 8) {
            uint4 v0 = __ldg(&in4[(size_t)s_idx[off + slot    ] + oct]);
            uint4 v1 = __ldg(&in4[(size_t)s_idx[off + slot + 4] + oct]);
            hacc(a, hmerge(v0, v1));
            off += 8; r -= 8;
        }
        if (r >= 4) {
            uint4 v = __ldg(&in4[(size_t)s_idx[off + slot] + oct]);
            hacc(a, v);
            off += 4; r -= 4;
        }
        { // predicated tail: 0..3 edges, zero uint4 == 0.0f halves
            uint4 t = make_uint4(0u, 0u, 0u, 0u);
            if (slot < r)
                t = __ldg(&in4[(size_t)s_idx[off + slot] + oct]);
            hacc(a, t);
        }
        __syncthreads();
    }

    // reduce the 4 slot groups (lanes oct, oct+8, oct+16, oct+24)
    #pragma unroll
    for (int k = 0; k < 8; ++k) {
        a[k] += __shfl_down_sync(0xffffffffu, a[k], 16);
        a[k] += __shfl_down_sync(0xffffffffu, a[k], 8);
    }

    if (slot == 0) {
        if (OUT_HALF) {
            uint4 o;
            o.x = h2u(__floats2half2_rn(a[0], a[1]));
            o.y = h2u(__floats2half2_rn(a[2], a[3]));
            o.z = h2u(__floats2half2_rn(a[4], a[5]));
            o.w = h2u(__floats2half2_rn(a[6], a[7]));
            ((uint4*)h_out)[(size_t)n * 8 + oct] = o;
        } else {
            float4* out4 = (float4*)h_out;
            out4[(size_t)n * 16 + oct * 2]     = make_float4(a[0], a[1], a[2], a[3]);
            out4[(size_t)n * 16 + oct * 2 + 1] = make_float4(a[4], a[5], a[6], a[7]);
        }
    }
}

extern "C" void kernel_launch(void* const* d_in, const int* in_sizes, int n_in,
                              void* d_out, int out_size) {
    const int*   src      = (const int*)d_in[0];
    const int*   dst      = (const int*)d_in[1];
    const float* features = (const float*)d_in[2];
    const float* W1       = (const float*)d_in[3];
    const float* W2       = (const float*)d_in[4];
    const float* W3       = (const float*)d_in[5];

    __half* t0; __half* t1;
    cudaGetSymbolAddress((void**)&t0, g_t0);
    cudaGetSymbolAddress((void**)&t1, g_t1);

    build_row_ptr_kernel<<<(N_NODES + 1 + 255) / 256, 256>>>(dst);
    wc_kernel<<<DIN, DIN>>>(W1, W2, W3);

    gemm_fwc_kernel<<<N_NODES / 64, 256>>>(features, t0);

    const int gblocks = N_NODES / 8;   // 5000
    gather_h_kernel<1><<<gblocks, 256>>>(src, t0, t1);
    gather_h_kernel<1><<<gblocks, 256>>>(src, t1, t0);
    gather_h_kernel<0><<<gblocks, 256>>>(src, t0, d_out);
}